// round 1
// baseline (speedup 1.0000x reference)
#include <cuda_runtime.h>
#include <cuda_bf16.h>
#include <cstdint>

#define BATCH 8
#define TLEN 256
#define DIM 256
#define NSTEP 12
#define NNEG 100
// C matrix: rows = B*T = 2048, cols = NSTEP*DIM = 3072
#define MROWS 2048
#define NCOLS 3072

// Scratch (static device globals: allowed; no allocation at runtime)
__device__ float g_C[MROWS * NCOLS];                 // queries for all steps
__device__ __nv_bfloat16 g_tn[MROWS * DIM];          // normalized targets (bf16)
__device__ float g_part[NSTEP * MROWS];              // per-sample loss partials

// ---------------------------------------------------------------------------
// Threefry-2x32 block cipher (exact JAX rotation/key schedule)
// ---------------------------------------------------------------------------
__device__ __forceinline__ void tf2x32(uint32_t k0, uint32_t k1,
                                       uint32_t x0, uint32_t x1,
                                       uint32_t &o0, uint32_t &o1) {
    uint32_t ks2 = k0 ^ k1 ^ 0x1BD11BDAu;
    x0 += k0; x1 += k1;
#define TFR(r) { x0 += x1; x1 = __funnelshift_l(x1, x1, (r)); x1 ^= x0; }
    TFR(13) TFR(15) TFR(26) TFR(6)   x0 += k1;  x1 += ks2 + 1u;
    TFR(17) TFR(29) TFR(16) TFR(24)  x0 += ks2; x1 += k0 + 2u;
    TFR(13) TFR(15) TFR(26) TFR(6)   x0 += k0;  x1 += k1 + 3u;
    TFR(17) TFR(29) TFR(16) TFR(24)  x0 += k1;  x1 += ks2 + 4u;
    TFR(13) TFR(15) TFR(26) TFR(6)   x0 += ks2; x1 += k0 + 5u;
#undef TFR
    o0 = x0; o1 = x1;
}

// Partitionable-threefry 32-bit random word for counter i (hi=0, lo=i):
__device__ __forceinline__ uint32_t tf_bits32(uint32_t k0, uint32_t k1, uint32_t i) {
    uint32_t a, b;
    tf2x32(k0, k1, 0u, i, a, b);
    return a ^ b;
}

// ---------------------------------------------------------------------------
// Kernel 1: normalize target rows, store bf16
// ---------------------------------------------------------------------------
__global__ void k_norm_targets(const float* __restrict__ tgt) {
    int gw = (blockIdx.x * blockDim.x + threadIdx.x) >> 5;
    int lane = threadIdx.x & 31;
    if (gw >= BATCH * TLEN) return;
    const float4* r = reinterpret_cast<const float4*>(tgt + (size_t)gw * DIM);
    float4 a = r[lane * 2];
    float4 b = r[lane * 2 + 1];
    float ss = a.x*a.x + a.y*a.y + a.z*a.z + a.w*a.w
             + b.x*b.x + b.y*b.y + b.z*b.z + b.w*b.w;
#pragma unroll
    for (int o = 16; o; o >>= 1) ss += __shfl_xor_sync(0xffffffffu, ss, o);
    float inv = 1.0f / fmaxf(sqrtf(ss), 1e-12f);
    __nv_bfloat162 p0 = __floats2bfloat162_rn(a.x * inv, a.y * inv);
    __nv_bfloat162 p1 = __floats2bfloat162_rn(a.z * inv, a.w * inv);
    __nv_bfloat162 p2 = __floats2bfloat162_rn(b.x * inv, b.y * inv);
    __nv_bfloat162 p3 = __floats2bfloat162_rn(b.z * inv, b.w * inv);
    uint4 u;
    u.x = *reinterpret_cast<uint32_t*>(&p0);
    u.y = *reinterpret_cast<uint32_t*>(&p1);
    u.z = *reinterpret_cast<uint32_t*>(&p2);
    u.w = *reinterpret_cast<uint32_t*>(&p3);
    reinterpret_cast<uint4*>(g_tn + (size_t)gw * DIM)[lane] = u;
}

// ---------------------------------------------------------------------------
// Kernel 2: C[2048, 3072] = A[2048, 256] * Bw[3072, 256]^T
//   (all 12 step-GEMMs fused; Bw = W viewed (12*256, 256) row-major)
//   128x128x8 tile, 256 threads, 8x8 per thread, split-tile float4 smem reads
// ---------------------------------------------------------------------------
__global__ __launch_bounds__(256, 2) void k_gemm(const float* __restrict__ A,
                                                 const float* __restrict__ Bw) {
    __shared__ float As[8][132];
    __shared__ float Bs[8][132];
    int bm = blockIdx.y * 128;
    int bn = blockIdx.x * 128;
    int tid = threadIdx.x;
    int tx = tid & 15, ty = tid >> 4;
    int lr = tid >> 1;            // 0..127 tile row for loads
    int lc = (tid & 1) * 4;       // 0 or 4
    const float* Ag = A + (size_t)(bm + lr) * DIM + lc;
    const float* Bg = Bw + (size_t)(bn + lr) * DIM + lc;
    float acc[8][8];
#pragma unroll
    for (int i = 0; i < 8; i++)
#pragma unroll
        for (int j = 0; j < 8; j++) acc[i][j] = 0.0f;

    for (int k0 = 0; k0 < DIM; k0 += 8) {
        float4 av = *reinterpret_cast<const float4*>(Ag + k0);
        float4 bv = *reinterpret_cast<const float4*>(Bg + k0);
        As[lc + 0][lr] = av.x; As[lc + 1][lr] = av.y;
        As[lc + 2][lr] = av.z; As[lc + 3][lr] = av.w;
        Bs[lc + 0][lr] = bv.x; Bs[lc + 1][lr] = bv.y;
        Bs[lc + 2][lr] = bv.z; Bs[lc + 3][lr] = bv.w;
        __syncthreads();
#pragma unroll
        for (int k = 0; k < 8; k++) {
            float ar[8], br[8];
            *reinterpret_cast<float4*>(&ar[0]) = *reinterpret_cast<const float4*>(&As[k][ty * 4]);
            *reinterpret_cast<float4*>(&ar[4]) = *reinterpret_cast<const float4*>(&As[k][64 + ty * 4]);
            *reinterpret_cast<float4*>(&br[0]) = *reinterpret_cast<const float4*>(&Bs[k][tx * 4]);
            *reinterpret_cast<float4*>(&br[4]) = *reinterpret_cast<const float4*>(&Bs[k][64 + tx * 4]);
#pragma unroll
            for (int i = 0; i < 8; i++)
#pragma unroll
                for (int j = 0; j < 8; j++) acc[i][j] = fmaf(ar[i], br[j], acc[i][j]);
        }
        __syncthreads();
    }
#pragma unroll
    for (int i = 0; i < 8; i++) {
        int m = bm + ((i < 4) ? (ty * 4 + i) : (64 + ty * 4 + i - 4));
        float* cp = g_C + (size_t)m * NCOLS + bn;
        *reinterpret_cast<float4*>(cp + tx * 4) =
            make_float4(acc[i][0], acc[i][1], acc[i][2], acc[i][3]);
        *reinterpret_cast<float4*>(cp + 64 + tx * 4) =
            make_float4(acc[i][4], acc[i][5], acc[i][6], acc[i][7]);
    }
}

// ---------------------------------------------------------------------------
// Kernel 3: add bias and L2-normalize each 256-wide query row (warp per row)
// ---------------------------------------------------------------------------
__global__ void k_bias_norm(const float* __restrict__ bias) {
    int gw = (blockIdx.x * blockDim.x + threadIdx.x) >> 5;
    int lane = threadIdx.x & 31;
    if (gw >= MROWS * NSTEP) return;
    int m = gw / NSTEP, s = gw % NSTEP;
    float* row = g_C + (size_t)m * NCOLS + (size_t)s * DIM;
    const float4* b4 = reinterpret_cast<const float4*>(bias + (size_t)s * DIM);
    float4 v0 = reinterpret_cast<float4*>(row)[lane * 2];
    float4 v1 = reinterpret_cast<float4*>(row)[lane * 2 + 1];
    float4 c0 = b4[lane * 2];
    float4 c1 = b4[lane * 2 + 1];
    v0.x += c0.x; v0.y += c0.y; v0.z += c0.z; v0.w += c0.w;
    v1.x += c1.x; v1.y += c1.y; v1.z += c1.z; v1.w += c1.w;
    float ss = v0.x*v0.x + v0.y*v0.y + v0.z*v0.z + v0.w*v0.w
             + v1.x*v1.x + v1.y*v1.y + v1.z*v1.z + v1.w*v1.w;
#pragma unroll
    for (int o = 16; o; o >>= 1) ss += __shfl_xor_sync(0xffffffffu, ss, o);
    float inv = 1.0f / fmaxf(sqrtf(ss), 1e-12f);
    v0.x *= inv; v0.y *= inv; v0.z *= inv; v0.w *= inv;
    v1.x *= inv; v1.y *= inv; v1.z *= inv; v1.w *= inv;
    reinterpret_cast<float4*>(row)[lane * 2] = v0;
    reinterpret_cast<float4*>(row)[lane * 2 + 1] = v1;
}

// ---------------------------------------------------------------------------
// Kernel 4: per-(step,b,t) InfoNCE partial loss
// ---------------------------------------------------------------------------
__global__ void k_loss() {
    int s = blockIdx.y + 1;           // step 1..12
    int T2 = TLEN - s;
    int bt = blockIdx.x;              // 0..2047
    int b = bt >> 8, t = bt & 255;
    int tid = threadIdx.x;
    __shared__ float logits[101];
    __shared__ int sidx[101];
    if (t >= T2) {
        if (tid == 0) g_part[(size_t)(s - 1) * MROWS + bt] = 0.0f;
        return;
    }
    uint32_t span = (uint32_t)(BATCH * T2);
    if (tid < 101) {
        int row;
        if (tid == 0) {
            row = b * TLEN + t + s;   // positive
        } else {
            // fold_in(key(1234), s)
            uint32_t k0, k1;
            tf2x32(0u, 1234u, 0u, (uint32_t)s, k0, k1);
            uint32_t n = span * NNEG;                       // B*T2*NNEG
            uint32_t i = (uint32_t)((b * T2 + t) * NNEG + (tid - 1));
            uint32_t hi = tf_bits32(k0, k1, i);
            uint32_t lo = tf_bits32(k0, k1, n + i);
            uint32_t m16 = 65536u % span;
            uint32_t mult = (m16 * m16) % span;
            uint32_t off = ((hi % span) * mult + (lo % span)) % span;
            uint32_t b2 = off / (uint32_t)T2;
            uint32_t t2 = off - b2 * (uint32_t)T2;
            row = (int)(b2 * TLEN + (uint32_t)s + t2);
        }
        sidx[tid] = row;
    }
    __syncthreads();

    int lane = tid & 31, w = tid >> 5;
    const float* qrow = g_C + (size_t)(b * TLEN + t) * NCOLS + (size_t)(s - 1) * DIM;
    const float4* q4 = reinterpret_cast<const float4*>(qrow);
    float4 qa = q4[lane * 2];
    float4 qb = q4[lane * 2 + 1];
    float ql[8] = {qa.x, qa.y, qa.z, qa.w, qb.x, qb.y, qb.z, qb.w};

    for (int item = w; item < 101; item += 8) {
        const uint4* p = reinterpret_cast<const uint4*>(g_tn + (size_t)sidx[item] * DIM);
        uint4 v = p[lane];
        const __nv_bfloat162* hh = reinterpret_cast<const __nv_bfloat162*>(&v);
        float dot = ql[0] * __low2float(hh[0]) + ql[1] * __high2float(hh[0])
                  + ql[2] * __low2float(hh[1]) + ql[3] * __high2float(hh[1])
                  + ql[4] * __low2float(hh[2]) + ql[5] * __high2float(hh[2])
                  + ql[6] * __low2float(hh[3]) + ql[7] * __high2float(hh[3]);
#pragma unroll
        for (int o = 16; o; o >>= 1) dot += __shfl_xor_sync(0xffffffffu, dot, o);
        if (lane == 0) logits[item] = dot * 10.0f;   // /TEMP
    }
    __syncthreads();

    if (w == 0) {
        float mx = -1e30f;
        for (int i = lane; i < 101; i += 32) mx = fmaxf(mx, logits[i]);
#pragma unroll
        for (int o = 16; o; o >>= 1) mx = fmaxf(mx, __shfl_xor_sync(0xffffffffu, mx, o));
        float sum = 0.0f;
        for (int i = lane; i < 101; i += 32) sum += __expf(logits[i] - mx);
#pragma unroll
        for (int o = 16; o; o >>= 1) sum += __shfl_xor_sync(0xffffffffu, sum, o);
        if (lane == 0) {
            float lse = mx + __logf(sum);
            g_part[(size_t)(s - 1) * MROWS + bt] =
                (lse - logits[0]) / (float)(NSTEP * BATCH * T2);
        }
    }
}

// ---------------------------------------------------------------------------
// Kernel 5: deterministic final reduction
// ---------------------------------------------------------------------------
__global__ void k_reduce(float* __restrict__ out) {
    __shared__ float sm[256];
    int tid = threadIdx.x;
    float s = 0.0f;
    for (int i = tid; i < NSTEP * MROWS; i += 256) s += g_part[i];
    sm[tid] = s;
    __syncthreads();
    for (int o = 128; o; o >>= 1) {
        if (tid < o) sm[tid] += sm[tid + o];
        __syncthreads();
    }
    if (tid == 0) out[0] = sm[0];
}

// ---------------------------------------------------------------------------
extern "C" void kernel_launch(void* const* d_in, const int* in_sizes, int n_in,
                              void* d_out, int out_size) {
    const float* ctx  = (const float*)d_in[0];
    const float* tgt  = (const float*)d_in[1];
    const float* W    = (const float*)d_in[2];
    const float* bias = (const float*)d_in[3];
    float* out = (float*)d_out;

    k_norm_targets<<<(BATCH * TLEN) / 8, 256>>>(tgt);
    k_gemm<<<dim3(NCOLS / 128, MROWS / 128), 256>>>(ctx, W);
    k_bias_norm<<<(MROWS * NSTEP) / 8, 256>>>(bias);
    k_loss<<<dim3(MROWS, NSTEP), 256>>>();
    k_reduce<<<1, 256>>>(out);
}